// round 9
// baseline (speedup 1.0000x reference)
#include <cuda_runtime.h>
#include <cstdint>

#define CH    16
#define OBLK  64
#define BBLK  32
#define KS0   32
#define KS12  16
#define BATCH 256
#define HID   512
#define DIN   2048

#define N0   (HID * DIN)
#define N1   (HID * HID)
#define OFF1 (N0)
#define OFF2 (N0 + N1)

typedef unsigned long long ull;

// ---- device scratch (no allocations allowed) ----
__device__ float g_rp[N0 + 2 * N1];     // transposed [i][o], r*sqrt(K)
__device__ float g_cp[N0 + 2 * N1];     // -t*r*sqrt(K)
__device__ float g_wk[N0 + 2 * N1];     // w/K
__device__ float g_xt[DIN * BATCH];     // x transposed [i][b]
__device__ float g_f1t[HID * BATCH];
__device__ float g_f2t[HID * BATCH];
__device__ float g_part[KS0 * BATCH * HID];

// ---- packed f32x2 helpers ----
__device__ __forceinline__ void fma2(ull& d, ull a, ull b, ull c) {
    asm("fma.rn.f32x2 %0, %1, %2, %3;" : "=l"(d) : "l"(a), "l"(b), "l"(c));
}
__device__ __forceinline__ void mul2(ull& d, ull a, ull b) {
    asm("mul.rn.f32x2 %0, %1, %2;" : "=l"(d) : "l"(a), "l"(b));
}
__device__ __forceinline__ void add2(ull& d, ull a, ull b) {
    asm("add.rn.f32x2 %0, %1, %2;" : "=l"(d) : "l"(a), "l"(b));
}
__device__ __forceinline__ ull pack2(float lo, float hi) {
    ull r; asm("mov.b64 %0, {%1, %2};" : "=l"(r) : "f"(lo), "f"(hi)); return r;
}
__device__ __forceinline__ void unpack2(float& lo, float& hi, ull v) {
    asm("mov.b64 {%0, %1}, %2;" : "=f"(lo), "=f"(hi) : "l"(v));
}
__device__ __forceinline__ float ex2f(float g) {
    float e; asm("ex2.approx.ftz.f32 %0, %1;" : "=f"(e) : "f"(g)); return e;
}
__device__ __forceinline__ uint32_t s2u(const void* p) {
    return (uint32_t)__cvta_generic_to_shared(p);
}
__device__ __forceinline__ void cpa16(void* dst, const float* src) {
    asm volatile("cp.async.cg.shared.global [%0], [%1], 16;"
                 :: "r"(s2u(dst)), "l"(src) : "memory");
}

// ---- fused setup: 3x param transform/transpose + x transpose ----
__device__ __forceinline__ void prep_block(const float* __restrict__ t,
                                           const float* __restrict__ s,
                                           const float* __restrict__ w,
                                           int I, int off, int i0, int o0,
                                           float sm[3][32][33]) {
    const int tx = threadIdx.x, ty = threadIdx.y;
    const float SQK = 0.84932177672f;          // sqrt(0.5*log2 e)
    const float IK = 1.38629436112f;           // 1/K
#pragma unroll
    for (int k = 0; k < 4; k++) {
        int ol = ty + k * 8;
        size_t idx = (size_t)(o0 + ol) * I + i0 + tx;
        float tv = t[idx], sv = s[idx], wv = w[idx];
        float den = 0.001f + log1pf(__expf(sv)) + 1e-8f;
        float r = SQK / den;
        sm[0][ol][tx] = r;
        sm[1][ol][tx] = -tv * r;
        sm[2][ol][tx] = wv * IK;
    }
    __syncthreads();
#pragma unroll
    for (int k = 0; k < 4; k++) {
        int il = ty + k * 8;
        size_t odx = (size_t)off + (size_t)(i0 + il) * HID + o0 + tx;
        g_rp[odx] = sm[0][tx][il];
        g_cp[odx] = sm[1][tx][il];
        g_wk[odx] = sm[2][tx][il];
    }
}

__global__ void setup_kernel(const float* __restrict__ t0, const float* __restrict__ s0,
                             const float* __restrict__ w0,
                             const float* __restrict__ t1, const float* __restrict__ s1,
                             const float* __restrict__ w1,
                             const float* __restrict__ t2, const float* __restrict__ s2,
                             const float* __restrict__ w2,
                             const float* __restrict__ x) {
    __shared__ float sm[3][32][33];
    const int bid = blockIdx.x;
    const int tx = threadIdx.x, ty = threadIdx.y;
    if (bid < 1024) {
        prep_block(t0, s0, w0, DIN, 0, (bid & 63) * 32, (bid >> 6) * 32, sm);
    } else if (bid < 1280) {
        int l = bid - 1024;
        prep_block(t1, s1, w1, HID, OFF1, (l & 15) * 32, (l >> 4) * 32, sm);
    } else if (bid < 1536) {
        int l = bid - 1280;
        prep_block(t2, s2, w2, HID, OFF2, (l & 15) * 32, (l >> 4) * 32, sm);
    } else {
        int l = bid - 1536;
        int i0 = (l & 63) * 32, b0 = (l >> 6) * 32;
#pragma unroll
        for (int k = 0; k < 4; k++)
            sm[0][ty + k * 8][tx] = x[(size_t)(b0 + ty + k * 8) * DIN + i0 + tx];
        __syncthreads();
#pragma unroll
        for (int k = 0; k < 4; k++)
            g_xt[(size_t)(i0 + ty + k * 8) * BATCH + b0 + tx] = sm[0][tx][ty + k * 8];
    }
}

// ---- wav kernel ----
struct __align__(16) Buf {
    float2 xd[CH][BBLK];   // 4KB: x duplicated per lane-pair
    float  rp[CH][OBLK];   // 4KB each
    float  cp[CH][OBLK];
    float  wk[CH][OBLK];
};                          // 16KB per buffer

__device__ __forceinline__ void stage_params(Buf* b, int i0, int o0, int off) {
    int c0 = threadIdx.x * 2;
#pragma unroll
    for (int j = 0; j < 2; j++) {
        int c = c0 + j, r = c >> 4, cc = (c & 15) * 4;
        size_t src = (size_t)off + (size_t)(i0 + r) * HID + o0 + cc;
        cpa16(&b->rp[r][cc], g_rp + src);
        cpa16(&b->cp[r][cc], g_cp + src);
        cpa16(&b->wk[r][cc], g_wk + src);
    }
    asm volatile("cp.async.commit_group;" ::: "memory");
}

__device__ __forceinline__ void ldg_x(float4& a, const float* xt, int i0, int b0) {
    const float* p = xt + (size_t)(i0 + (threadIdx.x >> 3)) * BATCH + b0 + (threadIdx.x & 7) * 4;
    a = *(const float4*)p;
}
__device__ __forceinline__ void sts_x(Buf* bf, float4 a) {
    float4* d = (float4*)&bf->xd[threadIdx.x >> 3][(threadIdx.x & 7) * 4];
    d[0] = make_float4(a.x, a.x, a.y, a.y);
    d[1] = make_float4(a.z, a.z, a.w, a.w);
}

// xsel: 0 -> g_xt, 1 -> g_f1t, 2 -> g_f2t
__global__ __launch_bounds__(128, 5) void wav_kernel(int I, int off, int xsel, int chunkI) {
    __shared__ Buf sb[2];
    const float* xt = (xsel == 0) ? g_xt : (xsel == 1) ? g_f1t : g_f2t;

    const int tid = threadIdx.x;
    const int og = tid & 15, bg = tid >> 4;
    const int o0 = blockIdx.x * OBLK;
    const int b0 = blockIdx.y * BBLK;
    const int ntile = chunkI / CH;
    const int ibase = blockIdx.z * chunkI;

    ull acc[2][4];
#pragma unroll
    for (int u = 0; u < 2; u++)
#pragma unroll
        for (int k = 0; k < 4; k++) acc[u][k] = 0ULL;

    stage_params(&sb[0], ibase, o0, off);
    float4 xa;
    ldg_x(xa, xt, ibase, b0);

    const ull SG = 0x8000000080000000ULL;
    const ull K2 = pack2(0.72134752044448f, 0.72134752044448f);  // K = 0.5*log2 e
    // poly-exp2 constants
    const ull MAG2  = pack2(12582912.0f, 12582912.0f);
    const ull NMAG2 = pack2(-12582912.0f, -12582912.0f);
    const ull PC1 = pack2(0.69314718056f, 0.69314718056f);
    const ull PC2 = pack2(0.24022650696f, 0.24022650696f);
    const ull PC3 = pack2(0.055504108664f, 0.055504108664f);
    const ull PC4 = pack2(0.0096181291076f, 0.0096181291076f);
    const ull ONE2 = pack2(1.0f, 1.0f);

    for (int t = 0; t < ntile; t++) {
        Buf* cur = &sb[t & 1];
        sts_x(cur, xa);
        if (t + 1 < ntile) {
            stage_params(&sb[(t + 1) & 1], ibase + (t + 1) * CH, o0, off);
            ldg_x(xa, xt, ibase + (t + 1) * CH, b0);
            asm volatile("cp.async.wait_group 1;" ::: "memory");
        } else {
            asm volatile("cp.async.wait_group 0;" ::: "memory");
        }
        __syncthreads();

#pragma unroll 2
        for (int i = 0; i < CH; i++) {
            ull xv[4];
            const ull* xr = (const ull*)&cur->xd[i][bg * 4];
#pragma unroll
            for (int k = 0; k < 4; k++) xv[k] = xr[k];
            const ull* rp2 = (const ull*)&cur->rp[i][og * 4];
            const ull* cp2 = (const ull*)&cur->cp[i][og * 4];
            const ull* wk2 = (const ull*)&cur->wk[i][og * 4];
#pragma unroll
            for (int u = 0; u < 2; u++) {
                ull rr = rp2[u], cc = cp2[u], kk = wk2[u], ww;
                mul2(ww, kk, K2);                 // w = (w/K)*K, amortized 1/4
#pragma unroll
                for (int k = 0; k < 4; k++) {
                    ull s, nu, p, e;
                    fma2(s, xv[k], rr, cc);       // s' = sqrtK*(x-t)/sc
                    ull ns = s ^ SG;              // -s'
                    mul2(nu, s, ns);              // nu = -K*s^2 (<= 0)
                    if (k == 0) {
                        // FMA-pipe exp2 (1/4 of units)
                        float nlo = __uint_as_float((uint32_t)nu);
                        float nhi = __uint_as_float((uint32_t)(nu >> 32));
                        nlo = fmaxf(nlo, -125.0f);
                        nhi = fmaxf(nhi, -125.0f);
                        ull nuc = pack2(nlo, nhi);
                        ull m, fi, f, tt;
                        add2(m, nuc, MAG2);        // MAG + round(nu)
                        add2(fi, m, NMAG2);        // round(nu) as float
                        ull nfi = fi ^ SG;
                        add2(f, nuc, nfi);         // frac, |f| <= 0.5
                        fma2(tt, f, PC4, PC3);
                        fma2(tt, f, tt, PC2);
                        fma2(tt, f, tt, PC1);
                        fma2(tt, f, tt, ONE2);     // 2^f
                        uint32_t mlo = (uint32_t)m, mhi = (uint32_t)(m >> 32);
                        float slo = __uint_as_float((mlo << 23) + 0x3F800000u);
                        float shi = __uint_as_float((mhi << 23) + 0x3F800000u);
                        float tlo = __uint_as_float((uint32_t)tt);
                        float thi = __uint_as_float((uint32_t)(tt >> 32));
                        e = pack2(tlo * slo, thi * shi);
                    } else {
                        float ga, gb; unpack2(ga, gb, nu);
                        e = pack2(ex2f(ga), ex2f(gb)); // MUFU exp
                    }
                    fma2(p, nu, kk, ww);          // w*(1-s^2)
                    fma2(acc[u][k], p, e, acc[u][k]);
                }
            }
        }
        __syncthreads();
    }

    float* dst = g_part + ((size_t)blockIdx.z * BATCH + b0 + bg * 4) * HID + o0 + og * 4;
#pragma unroll
    for (int k = 0; k < 4; k++) {
        float4 v;
        unpack2(v.x, v.y, acc[0][k]);
        unpack2(v.z, v.w, acc[1][k]);
        *(float4*)(dst + (size_t)k * HID) = v;
    }
}

// ---- split-K reduce + SiLU + LayerNorm (+ classifier) ----
__global__ __launch_bounds__(128) void reduce_kernel(const float* __restrict__ gamma,
                                                     const float* __restrict__ beta,
                                                     const float* __restrict__ cw,
                                                     const float* __restrict__ cb,
                                                     float* __restrict__ out,
                                                     int outsel, int nks) {
    const int b = blockIdx.x;
    const int tid = threadIdx.x;
    const int wid = tid >> 5, lane = tid & 31;
    __shared__ float r1[4], r2[4];

    const float4* src = (const float4*)(g_part + (size_t)b * HID + tid * 4);
    float4 z = make_float4(0.f, 0.f, 0.f, 0.f);
#pragma unroll 4
    for (int k = 0; k < nks; k++) {
        float4 v = src[(size_t)k * (BATCH * HID / 4)];
        z.x += v.x; z.y += v.y; z.z += v.z; z.w += v.w;
    }
    float a[4];
    float lsum = 0.f, lsq = 0.f;
#pragma unroll
    for (int j = 0; j < 4; j++) {
        float zz = ((float*)&z)[j];
        float sig = 1.0f / (1.0f + __expf(-zz));
        float av = zz * sig;
        a[j] = av;
        lsum += av;
        lsq = fmaf(av, av, lsq);
    }
#pragma unroll
    for (int off = 16; off; off >>= 1) {
        lsum += __shfl_xor_sync(0xffffffffu, lsum, off);
        lsq  += __shfl_xor_sync(0xffffffffu, lsq, off);
    }
    if (lane == 0) { r1[wid] = lsum; r2[wid] = lsq; }
    __syncthreads();
    float tsum = r1[0] + r1[1] + r1[2] + r1[3];
    float tsq  = r2[0] + r2[1] + r2[2] + r2[3];
    float mean = tsum * (1.0f / HID);
    float var  = tsq * (1.0f / HID) - mean * mean;
    float rstd = rsqrtf(var + 1e-5f);

    float4 gm = ((const float4*)gamma)[tid];
    float4 bt = ((const float4*)beta)[tid];
    float d0 = 0.f, d1 = 0.f;
    float* ft = (outsel == 1) ? g_f1t : g_f2t;
#pragma unroll
    for (int j = 0; j < 4; j++) {
        int o = tid * 4 + j;
        float y = (a[j] - mean) * rstd * ((float*)&gm)[j] + ((float*)&bt)[j];
        if (outsel == 0) {
            d0 = fmaf(y, cw[o], d0);
            d1 = fmaf(y, cw[HID + o], d1);
        } else {
            ft[(size_t)o * BATCH + b] = y;
        }
    }
    if (outsel == 0) {
#pragma unroll
        for (int off = 16; off; off >>= 1) {
            d0 += __shfl_xor_sync(0xffffffffu, d0, off);
            d1 += __shfl_xor_sync(0xffffffffu, d1, off);
        }
        __syncthreads();
        if (lane == 0) { r1[wid] = d0; r2[wid] = d1; }
        __syncthreads();
        if (tid == 0) {
            out[b * 2 + 0] = r1[0] + r1[1] + r1[2] + r1[3] + cb[0];
            out[b * 2 + 1] = r2[0] + r2[1] + r2[2] + r2[3] + cb[1];
        }
    }
}

extern "C" void kernel_launch(void* const* d_in, const int* in_sizes, int n_in,
                              void* d_out, int out_size) {
    const float* x  = (const float*)d_in[0];
    const float* t0 = (const float*)d_in[1];
    const float* s0 = (const float*)d_in[2];
    const float* w0 = (const float*)d_in[3];
    const float* g0 = (const float*)d_in[4];
    const float* b0 = (const float*)d_in[5];
    const float* t1 = (const float*)d_in[6];
    const float* s1 = (const float*)d_in[7];
    const float* w1 = (const float*)d_in[8];
    const float* g1 = (const float*)d_in[9];
    const float* b1 = (const float*)d_in[10];
    const float* t2 = (const float*)d_in[11];
    const float* s2 = (const float*)d_in[12];
    const float* w2 = (const float*)d_in[13];
    const float* g2 = (const float*)d_in[14];
    const float* b2 = (const float*)d_in[15];
    const float* cw = (const float*)d_in[16];
    const float* cb = (const float*)d_in[17];
    float* out = (float*)d_out;

    setup_kernel<<<2048, dim3(32, 8)>>>(t0, s0, w0, t1, s1, w1, t2, s2, w2, x);

    dim3 gw0(HID / OBLK, BATCH / BBLK, KS0);   // (8, 8, 32) = 2048 blocks, ntile=4
    dim3 gw12(HID / OBLK, BATCH / BBLK, KS12); // (8, 8, 16) = 1024 blocks, ntile=2

    wav_kernel<<<gw0, 128>>>(DIN, 0, 0, DIN / KS0);
    reduce_kernel<<<BATCH, 128>>>(g0, b0, cw, cb, out, 1, KS0);

    wav_kernel<<<gw12, 128>>>(HID, OFF1, 1, HID / KS12);
    reduce_kernel<<<BATCH, 128>>>(g1, b1, cw, cb, out, 2, KS12);

    wav_kernel<<<gw12, 128>>>(HID, OFF2, 2, HID / KS12);
    reduce_kernel<<<BATCH, 128>>>(g2, b2, cw, cb, out, 0, KS12);
}

// round 11
// speedup vs baseline: 1.2302x; 1.2302x over previous
#include <cuda_runtime.h>
#include <cstdint>

#define CH    16
#define OBLK  64
#define BBLK  64
#define KS    32
#define BATCH 256
#define HID   512
#define DIN   2048

#define N0   (HID * DIN)
#define N1   (HID * HID)
#define OFF1 (N0)
#define OFF2 (N0 + N1)

typedef unsigned long long ull;

// ---- device scratch (no allocations allowed) ----
__device__ float g_rp[N0 + 2 * N1];     // transposed [i][o], r*sqrt(K)
__device__ float g_cp[N0 + 2 * N1];     // -t*r*sqrt(K)
__device__ float g_wk[N0 + 2 * N1];     // w/K
__device__ float g_xt[DIN * BATCH];     // x transposed [i][b]
__device__ float g_f1t[HID * BATCH];
__device__ float g_f2t[HID * BATCH];
__device__ float g_part[KS * BATCH * HID];

// ---- packed f32x2 helpers ----
__device__ __forceinline__ void fma2(ull& d, ull a, ull b, ull c) {
    asm("fma.rn.f32x2 %0, %1, %2, %3;" : "=l"(d) : "l"(a), "l"(b), "l"(c));
}
__device__ __forceinline__ void mul2(ull& d, ull a, ull b) {
    asm("mul.rn.f32x2 %0, %1, %2;" : "=l"(d) : "l"(a), "l"(b));
}
__device__ __forceinline__ ull pack2(float lo, float hi) {
    ull r; asm("mov.b64 %0, {%1, %2};" : "=l"(r) : "f"(lo), "f"(hi)); return r;
}
__device__ __forceinline__ void unpack2(float& lo, float& hi, ull v) {
    asm("mov.b64 {%0, %1}, %2;" : "=f"(lo), "=f"(hi) : "l"(v));
}
__device__ __forceinline__ float ex2f(float g) {
    float e; asm("ex2.approx.ftz.f32 %0, %1;" : "=f"(e) : "f"(g)); return e;
}
__device__ __forceinline__ uint32_t s2u(const void* p) {
    return (uint32_t)__cvta_generic_to_shared(p);
}
__device__ __forceinline__ void cpa16(void* dst, const float* src) {
    asm volatile("cp.async.cg.shared.global [%0], [%1], 16;"
                 :: "r"(s2u(dst)), "l"(src) : "memory");
}

// ---- fused setup: 3x param transform/transpose + x transpose ----
__device__ __forceinline__ void prep_block(const float* __restrict__ t,
                                           const float* __restrict__ s,
                                           const float* __restrict__ w,
                                           int I, int off, int i0, int o0,
                                           float sm[3][32][33]) {
    const int tx = threadIdx.x, ty = threadIdx.y;
    const float SQK = 0.84932177672f;          // sqrt(0.5*log2 e)
    const float IK = 1.38629436112f;           // 1/K
#pragma unroll
    for (int k = 0; k < 4; k++) {
        int ol = ty + k * 8;
        size_t idx = (size_t)(o0 + ol) * I + i0 + tx;
        float tv = t[idx], sv = s[idx], wv = w[idx];
        float den = 0.001f + log1pf(__expf(sv)) + 1e-8f;
        float r = SQK / den;
        sm[0][ol][tx] = r;
        sm[1][ol][tx] = -tv * r;
        sm[2][ol][tx] = wv * IK;
    }
    __syncthreads();
#pragma unroll
    for (int k = 0; k < 4; k++) {
        int il = ty + k * 8;
        size_t odx = (size_t)off + (size_t)(i0 + il) * HID + o0 + tx;
        g_rp[odx] = sm[0][tx][il];
        g_cp[odx] = sm[1][tx][il];
        g_wk[odx] = sm[2][tx][il];
    }
}

__global__ void setup_kernel(const float* __restrict__ t0, const float* __restrict__ s0,
                             const float* __restrict__ w0,
                             const float* __restrict__ t1, const float* __restrict__ s1,
                             const float* __restrict__ w1,
                             const float* __restrict__ t2, const float* __restrict__ s2,
                             const float* __restrict__ w2,
                             const float* __restrict__ x) {
    __shared__ float sm[3][32][33];
    const int bid = blockIdx.x;
    const int tx = threadIdx.x, ty = threadIdx.y;
    if (bid < 1024) {
        prep_block(t0, s0, w0, DIN, 0, (bid & 63) * 32, (bid >> 6) * 32, sm);
    } else if (bid < 1280) {
        int l = bid - 1024;
        prep_block(t1, s1, w1, HID, OFF1, (l & 15) * 32, (l >> 4) * 32, sm);
    } else if (bid < 1536) {
        int l = bid - 1280;
        prep_block(t2, s2, w2, HID, OFF2, (l & 15) * 32, (l >> 4) * 32, sm);
    } else {
        int l = bid - 1536;
        int i0 = (l & 63) * 32, b0 = (l >> 6) * 32;
#pragma unroll
        for (int k = 0; k < 4; k++)
            sm[0][ty + k * 8][tx] = x[(size_t)(b0 + ty + k * 8) * DIN + i0 + tx];
        __syncthreads();
#pragma unroll
        for (int k = 0; k < 4; k++)
            g_xt[(size_t)(i0 + ty + k * 8) * BATCH + b0 + tx] = sm[0][tx][ty + k * 8];
    }
}

// ---- wav kernel ----
struct __align__(16) Buf {
    float2 xd[CH][BBLK];   // 8KB: x duplicated per lane-pair
    float  rp[CH][OBLK];   // 4KB each
    float  cp[CH][OBLK];
    float  wk[CH][OBLK];
};                          // 20KB per buffer

__device__ __forceinline__ void stage_params(Buf* b, int i0, int o0, int off) {
    int c0 = threadIdx.x * 2;
#pragma unroll
    for (int j = 0; j < 2; j++) {
        int c = c0 + j, r = c >> 4, cc = (c & 15) * 4;
        size_t src = (size_t)off + (size_t)(i0 + r) * HID + o0 + cc;
        cpa16(&b->rp[r][cc], g_rp + src);
        cpa16(&b->cp[r][cc], g_cp + src);
        cpa16(&b->wk[r][cc], g_wk + src);
    }
    asm volatile("cp.async.commit_group;" ::: "memory");
}

__device__ __forceinline__ void ldg_x(float4& a, float4& b, const float* xt, int i0, int b0) {
    const float* p = xt + (size_t)(i0 + (threadIdx.x >> 3)) * BATCH + b0 + (threadIdx.x & 7) * 8;
    a = *(const float4*)p;
    b = *(const float4*)(p + 4);
}
__device__ __forceinline__ void sts_x(Buf* bf, float4 a, float4 b) {
    float4* d = (float4*)&bf->xd[threadIdx.x >> 3][(threadIdx.x & 7) * 8];
    d[0] = make_float4(a.x, a.x, a.y, a.y);
    d[1] = make_float4(a.z, a.z, a.w, a.w);
    d[2] = make_float4(b.x, b.x, b.y, b.y);
    d[3] = make_float4(b.z, b.z, b.w, b.w);
}

// xsel: 0 -> g_xt, 1 -> g_f1t, 2 -> g_f2t
__global__ __launch_bounds__(128, 5) void wav_kernel(int I, int off, int xsel) {
    __shared__ Buf sb[2];
    const float* xt = (xsel == 0) ? g_xt : (xsel == 1) ? g_f1t : g_f2t;

    const int tid = threadIdx.x;
    const int og = tid & 15, bg = tid >> 4;
    const int o0 = blockIdx.x * OBLK;
    const int b0 = blockIdx.y * BBLK;
    const int chunkI = I / KS;
    const int ntile = chunkI / CH;
    const int ibase = blockIdx.z * chunkI;

    ull acc[2][8];
#pragma unroll
    for (int u = 0; u < 2; u++)
#pragma unroll
        for (int k = 0; k < 8; k++) acc[u][k] = 0ULL;

    if (xsel != 0) {
        // params depend only on setup (long complete); issue before grid-dep sync
        stage_params(&sb[0], ibase, o0, off);
        cudaGridDependencySynchronize();   // wait for producer (reduce_k) before f-tile read
    } else {
        cudaGridDependencySynchronize();   // wait for setup
        stage_params(&sb[0], ibase, o0, off);
    }
    float4 xa, xb;
    ldg_x(xa, xb, xt, ibase, b0);

    const ull SG = 0x8000000080000000ULL;
    const ull K2 = pack2(0.72134752044448f, 0.72134752044448f);  // K = 0.5*log2 e

    for (int t = 0; t < ntile; t++) {
        Buf* cur = &sb[t & 1];
        sts_x(cur, xa, xb);
        if (t + 1 < ntile) {
            stage_params(&sb[(t + 1) & 1], ibase + (t + 1) * CH, o0, off);
            ldg_x(xa, xb, xt, ibase + (t + 1) * CH, b0);
            asm volatile("cp.async.wait_group 1;" ::: "memory");
        } else {
            asm volatile("cp.async.wait_group 0;" ::: "memory");
        }
        __syncthreads();

#pragma unroll 2
        for (int i = 0; i < CH; i++) {
            ull xv[8];
            const ull* xr = (const ull*)&cur->xd[i][bg * 8];
#pragma unroll
            for (int k = 0; k < 8; k++) xv[k] = xr[k];
            const ull* rp2 = (const ull*)&cur->rp[i][og * 4];
            const ull* cp2 = (const ull*)&cur->cp[i][og * 4];
            const ull* wk2 = (const ull*)&cur->wk[i][og * 4];
#pragma unroll
            for (int u = 0; u < 2; u++) {
                ull rr = rp2[u], cc = cp2[u], kk = wk2[u], ww;
                mul2(ww, kk, K2);                 // w = (w/K)*K, amortized 1/8
#pragma unroll
                for (int k = 0; k < 8; k++) {
                    ull s, nu, p;
                    fma2(s, xv[k], rr, cc);       // s' = sqrtK*(x-t)/sc
                    ull ns = s ^ SG;              // -s'
                    mul2(nu, s, ns);              // nu = -K*s^2
                    float ga, gb; unpack2(ga, gb, nu);
                    ull e = pack2(ex2f(ga), ex2f(gb)); // exp(-s^2/2)
                    fma2(p, nu, kk, ww);          // w*(1-s^2)
                    fma2(acc[u][k], p, e, acc[u][k]);
                }
            }
        }
        __syncthreads();
    }

    float* dst = g_part + ((size_t)blockIdx.z * BATCH + b0 + bg * 8) * HID + o0 + og * 4;
#pragma unroll
    for (int k = 0; k < 8; k++) {
        float4 v;
        unpack2(v.x, v.y, acc[0][k]);
        unpack2(v.z, v.w, acc[1][k]);
        *(float4*)(dst + (size_t)k * HID) = v;
    }
}

// ---- split-K reduce + SiLU + LayerNorm (+ classifier) ----
__global__ __launch_bounds__(128) void reduce_kernel(const float* __restrict__ gamma,
                                                     const float* __restrict__ beta,
                                                     const float* __restrict__ cw,
                                                     const float* __restrict__ cb,
                                                     float* __restrict__ out,
                                                     int outsel) {
    const int b = blockIdx.x;
    const int tid = threadIdx.x;
    const int wid = tid >> 5, lane = tid & 31;
    __shared__ float r1[4], r2[4];

    // independent prologue loads before grid-dep sync
    float4 gm = ((const float4*)gamma)[tid];
    float4 bt = ((const float4*)beta)[tid];
    float4 cwa = make_float4(0.f, 0.f, 0.f, 0.f), cwb = cwa;
    if (outsel == 0) {
        cwa = ((const float4*)cw)[tid];
        cwb = ((const float4*)(cw + HID))[tid];
    }
    cudaGridDependencySynchronize();   // wait for wav partials

    const float4* src = (const float4*)(g_part + (size_t)b * HID + tid * 4);
    float4 z = make_float4(0.f, 0.f, 0.f, 0.f);
#pragma unroll
    for (int k = 0; k < KS; k++) {
        float4 v = src[(size_t)k * (BATCH * HID / 4)];
        z.x += v.x; z.y += v.y; z.z += v.z; z.w += v.w;
    }
    float a[4];
    float lsum = 0.f, lsq = 0.f;
#pragma unroll
    for (int j = 0; j < 4; j++) {
        float zz = ((float*)&z)[j];
        float sig = 1.0f / (1.0f + __expf(-zz));
        float av = zz * sig;
        a[j] = av;
        lsum += av;
        lsq = fmaf(av, av, lsq);
    }
#pragma unroll
    for (int off = 16; off; off >>= 1) {
        lsum += __shfl_xor_sync(0xffffffffu, lsum, off);
        lsq  += __shfl_xor_sync(0xffffffffu, lsq, off);
    }
    if (lane == 0) { r1[wid] = lsum; r2[wid] = lsq; }
    __syncthreads();
    float tsum = r1[0] + r1[1] + r1[2] + r1[3];
    float tsq  = r2[0] + r2[1] + r2[2] + r2[3];
    float mean = tsum * (1.0f / HID);
    float var  = tsq * (1.0f / HID) - mean * mean;
    float rstd = rsqrtf(var + 1e-5f);

    float d0 = 0.f, d1 = 0.f;
    float* ft = (outsel == 1) ? g_f1t : g_f2t;
#pragma unroll
    for (int j = 0; j < 4; j++) {
        int o = tid * 4 + j;
        float y = (a[j] - mean) * rstd * ((float*)&gm)[j] + ((float*)&bt)[j];
        if (outsel == 0) {
            d0 = fmaf(y, ((float*)&cwa)[j], d0);
            d1 = fmaf(y, ((float*)&cwb)[j], d1);
        } else {
            ft[(size_t)o * BATCH + b] = y;
        }
    }
    if (outsel == 0) {
#pragma unroll
        for (int off = 16; off; off >>= 1) {
            d0 += __shfl_xor_sync(0xffffffffu, d0, off);
            d1 += __shfl_xor_sync(0xffffffffu, d1, off);
        }
        __syncthreads();
        if (lane == 0) { r1[wid] = d0; r2[wid] = d1; }
        __syncthreads();
        if (tid == 0) {
            out[b * 2 + 0] = r1[0] + r1[1] + r1[2] + r1[3] + cb[0];
            out[b * 2 + 1] = r2[0] + r2[1] + r2[2] + r2[3] + cb[1];
        }
    }
}

// helper: launch with PDL (programmatic stream serialization)
template <typename... Args>
static void launch_pdl(void (*kern)(Args...), dim3 grid, dim3 block, Args... args) {
    cudaLaunchConfig_t cfg = {};
    cfg.gridDim = grid;
    cfg.blockDim = block;
    cfg.dynamicSmemBytes = 0;
    cfg.stream = 0;
    cudaLaunchAttribute attr[1];
    attr[0].id = cudaLaunchAttributeProgrammaticStreamSerialization;
    attr[0].val.programmaticStreamSerializationAllowed = 1;
    cfg.attrs = attr;
    cfg.numAttrs = 1;
    cudaLaunchKernelEx(&cfg, kern, args...);
}

extern "C" void kernel_launch(void* const* d_in, const int* in_sizes, int n_in,
                              void* d_out, int out_size) {
    const float* x  = (const float*)d_in[0];
    const float* t0 = (const float*)d_in[1];
    const float* s0 = (const float*)d_in[2];
    const float* w0 = (const float*)d_in[3];
    const float* g0 = (const float*)d_in[4];
    const float* b0 = (const float*)d_in[5];
    const float* t1 = (const float*)d_in[6];
    const float* s1 = (const float*)d_in[7];
    const float* w1 = (const float*)d_in[8];
    const float* g1 = (const float*)d_in[9];
    const float* b1 = (const float*)d_in[10];
    const float* t2 = (const float*)d_in[11];
    const float* s2 = (const float*)d_in[12];
    const float* w2 = (const float*)d_in[13];
    const float* g2 = (const float*)d_in[14];
    const float* b2 = (const float*)d_in[15];
    const float* cw = (const float*)d_in[16];
    const float* cb = (const float*)d_in[17];
    float* out = (float*)d_out;

    setup_kernel<<<2048, dim3(32, 8)>>>(t0, s0, w0, t1, s1, w1, t2, s2, w2, x);

    dim3 gw(HID / OBLK, BATCH / BBLK, KS);  // (8, 4, 32) = 1024 blocks
    dim3 bw(128, 1, 1);
    dim3 gr(BATCH, 1, 1);

    launch_pdl(wav_kernel, gw, bw, DIN, 0, 0);
    launch_pdl(reduce_kernel, gr, bw, g0, b0, cw, cb, out, 1);

    launch_pdl(wav_kernel, gw, bw, HID, OFF1, 1);
    launch_pdl(reduce_kernel, gr, bw, g1, b1, cw, cb, out, 2);

    launch_pdl(wav_kernel, gw, bw, HID, OFF2, 2);
    launch_pdl(reduce_kernel, gr, bw, g2, b2, cw, cb, out, 0);
}

// round 12
// speedup vs baseline: 1.2723x; 1.0342x over previous
#include <cuda_runtime.h>
#include <cstdint>

#define CH    16
#define OBLK  64
#define BBLK  32
#define KS    32
#define BATCH 256
#define HID   512
#define DIN   2048

#define N0   (HID * DIN)
#define N1   (HID * HID)
#define OFF1 (N0)
#define OFF2 (N0 + N1)

typedef unsigned long long ull;

// ---- device scratch (no allocations allowed) ----
__device__ float g_rp[N0 + 2 * N1];     // transposed [i][o], r*sqrt(K)
__device__ float g_cp[N0 + 2 * N1];     // -t*r*sqrt(K)
__device__ float g_wk[N0 + 2 * N1];     // w/K
__device__ float g_xt[DIN * BATCH];     // x transposed [i][b]
__device__ float g_f1t[HID * BATCH];
__device__ float g_f2t[HID * BATCH];
__device__ float g_part[KS * BATCH * HID];

// ---- packed f32x2 helpers ----
__device__ __forceinline__ void fma2(ull& d, ull a, ull b, ull c) {
    asm("fma.rn.f32x2 %0, %1, %2, %3;" : "=l"(d) : "l"(a), "l"(b), "l"(c));
}
__device__ __forceinline__ void mul2(ull& d, ull a, ull b) {
    asm("mul.rn.f32x2 %0, %1, %2;" : "=l"(d) : "l"(a), "l"(b));
}
__device__ __forceinline__ ull pack2(float lo, float hi) {
    ull r; asm("mov.b64 %0, {%1, %2};" : "=l"(r) : "f"(lo), "f"(hi)); return r;
}
__device__ __forceinline__ void unpack2(float& lo, float& hi, ull v) {
    asm("mov.b64 {%0, %1}, %2;" : "=f"(lo), "=f"(hi) : "l"(v));
}
__device__ __forceinline__ float ex2f(float g) {
    float e; asm("ex2.approx.ftz.f32 %0, %1;" : "=f"(e) : "f"(g)); return e;
}
__device__ __forceinline__ uint32_t s2u(const void* p) {
    return (uint32_t)__cvta_generic_to_shared(p);
}
__device__ __forceinline__ void cpa16(void* dst, const float* src) {
    asm volatile("cp.async.cg.shared.global [%0], [%1], 16;"
                 :: "r"(s2u(dst)), "l"(src) : "memory");
}
#define CPA_COMMIT() asm volatile("cp.async.commit_group;" ::: "memory")

// ---- fused setup: 3x param transform/transpose + x transpose ----
__device__ __forceinline__ void prep_block(const float* __restrict__ t,
                                           const float* __restrict__ s,
                                           const float* __restrict__ w,
                                           int I, int off, int i0, int o0,
                                           float sm[3][32][33]) {
    const int tx = threadIdx.x, ty = threadIdx.y;
    const float SQK = 0.84932177672f;          // sqrt(0.5*log2 e)
    const float IK = 1.38629436112f;           // 1/K
#pragma unroll
    for (int k = 0; k < 4; k++) {
        int ol = ty + k * 8;
        size_t idx = (size_t)(o0 + ol) * I + i0 + tx;
        float tv = t[idx], sv = s[idx], wv = w[idx];
        float den = 0.001f + log1pf(__expf(sv)) + 1e-8f;
        float r = SQK / den;
        sm[0][ol][tx] = r;
        sm[1][ol][tx] = -tv * r;
        sm[2][ol][tx] = wv * IK;
    }
    __syncthreads();
#pragma unroll
    for (int k = 0; k < 4; k++) {
        int il = ty + k * 8;
        size_t odx = (size_t)off + (size_t)(i0 + il) * HID + o0 + tx;
        g_rp[odx] = sm[0][tx][il];
        g_cp[odx] = sm[1][tx][il];
        g_wk[odx] = sm[2][tx][il];
    }
}

__global__ void setup_kernel(const float* __restrict__ t0, const float* __restrict__ s0,
                             const float* __restrict__ w0,
                             const float* __restrict__ t1, const float* __restrict__ s1,
                             const float* __restrict__ w1,
                             const float* __restrict__ t2, const float* __restrict__ s2,
                             const float* __restrict__ w2,
                             const float* __restrict__ x) {
    __shared__ float sm[3][32][33];
    const int bid = blockIdx.x;
    const int tx = threadIdx.x, ty = threadIdx.y;
    if (bid < 1024) {
        prep_block(t0, s0, w0, DIN, 0, (bid & 63) * 32, (bid >> 6) * 32, sm);
    } else if (bid < 1280) {
        int l = bid - 1024;
        prep_block(t1, s1, w1, HID, OFF1, (l & 15) * 32, (l >> 4) * 32, sm);
    } else if (bid < 1536) {
        int l = bid - 1280;
        prep_block(t2, s2, w2, HID, OFF2, (l & 15) * 32, (l >> 4) * 32, sm);
    } else {
        int l = bid - 1536;
        int i0 = (l & 63) * 32, b0 = (l >> 6) * 32;
#pragma unroll
        for (int k = 0; k < 4; k++)
            sm[0][ty + k * 8][tx] = x[(size_t)(b0 + ty + k * 8) * DIN + i0 + tx];
        __syncthreads();
#pragma unroll
        for (int k = 0; k < 4; k++)
            g_xt[(size_t)(i0 + ty + k * 8) * BATCH + b0 + tx] = sm[0][tx][ty + k * 8];
    }
}

// ---- wav kernel ----
struct __align__(16) Buf {
    float xs[CH][BBLK];    // 2KB: x unduplicated
    float rp[CH][OBLK];    // 4KB each
    float cp[CH][OBLK];
    float wk[CH][OBLK];
};                          // 14KB per buffer

__device__ __forceinline__ void stage_params(Buf* b, int i0, int o0, int off) {
    int c0 = threadIdx.x * 2;
#pragma unroll
    for (int j = 0; j < 2; j++) {
        int c = c0 + j, r = c >> 4, cc = (c & 15) * 4;
        size_t src = (size_t)off + (size_t)(i0 + r) * HID + o0 + cc;
        cpa16(&b->rp[r][cc], g_rp + src);
        cpa16(&b->cp[r][cc], g_cp + src);
        cpa16(&b->wk[r][cc], g_wk + src);
    }
}
__device__ __forceinline__ void stage_x(Buf* b, const float* xt, int i0, int b0) {
    int row = threadIdx.x >> 3, col = (threadIdx.x & 7) * 4;
    cpa16(&b->xs[row][col], xt + (size_t)(i0 + row) * BATCH + b0 + col);
}

// xsel: 0 -> g_xt, 1 -> g_f1t, 2 -> g_f2t
__global__ __launch_bounds__(128, 7) void wav_kernel(int I, int off, int xsel, int chunkI) {
    __shared__ Buf sb[2];
    const float* xt = (xsel == 0) ? g_xt : (xsel == 1) ? g_f1t : g_f2t;

    const int tid = threadIdx.x;
    const int og = tid & 15, bg = tid >> 4;    // 16 o-groups of 4, 8 b-groups of 4
    const int o0 = blockIdx.x * OBLK;
    const int b0 = blockIdx.y * BBLK;
    const int ntile = chunkI / CH;
    const int ibase = blockIdx.z * chunkI;

    ull acc[2][4];
#pragma unroll
    for (int u = 0; u < 2; u++)
#pragma unroll
        for (int k = 0; k < 4; k++) acc[u][k] = 0ULL;

    if (xsel != 0) {
        // params depend only on setup (long complete); issue before grid-dep sync
        stage_params(&sb[0], ibase, o0, off);
        cudaGridDependencySynchronize();   // wait for producer before f-tile read
        stage_x(&sb[0], xt, ibase, b0);
    } else {
        cudaGridDependencySynchronize();   // wait for setup
        stage_params(&sb[0], ibase, o0, off);
        stage_x(&sb[0], xt, ibase, b0);
    }
    CPA_COMMIT();

    const ull SG = 0x8000000080000000ULL;
    const ull K2 = pack2(0.72134752044448f, 0.72134752044448f);  // K = 0.5*log2 e

    for (int t = 0; t < ntile; t++) {
        Buf* cur = &sb[t & 1];
        if (t + 1 < ntile) {
            Buf* nxt = &sb[(t + 1) & 1];
            stage_params(nxt, ibase + (t + 1) * CH, o0, off);
            stage_x(nxt, xt, ibase + (t + 1) * CH, b0);
            CPA_COMMIT();
            asm volatile("cp.async.wait_group 1;" ::: "memory");
        } else {
            asm volatile("cp.async.wait_group 0;" ::: "memory");
        }
        __syncthreads();

#pragma unroll 2
        for (int i = 0; i < CH; i++) {
            float4 x4 = *(const float4*)&cur->xs[i][bg * 4];
            ull xp[4];
            xp[0] = pack2(x4.x, x4.x); xp[1] = pack2(x4.y, x4.y);
            xp[2] = pack2(x4.z, x4.z); xp[3] = pack2(x4.w, x4.w);
            const ull* rp2 = (const ull*)&cur->rp[i][og * 4];
            const ull* cp2 = (const ull*)&cur->cp[i][og * 4];
            const ull* wk2 = (const ull*)&cur->wk[i][og * 4];
#pragma unroll
            for (int u = 0; u < 2; u++) {
                ull rr = rp2[u], cc = cp2[u], kk = wk2[u], ww;
                mul2(ww, kk, K2);                 // w = (w/K)*K, amortized 1/4
#pragma unroll
                for (int k = 0; k < 4; k++) {
                    ull s, nu, p;
                    fma2(s, xp[k], rr, cc);       // s' = sqrtK*(x-t)/sc
                    ull ns = s ^ SG;              // -s'
                    mul2(nu, s, ns);              // nu = -K*s^2
                    float ga, gb; unpack2(ga, gb, nu);
                    ull e = pack2(ex2f(ga), ex2f(gb)); // exp(-s^2/2)
                    fma2(p, nu, kk, ww);          // w*(1-s^2)
                    fma2(acc[u][k], p, e, acc[u][k]);
                }
            }
        }
        __syncthreads();
    }

    float* dst = g_part + ((size_t)blockIdx.z * BATCH + b0 + bg * 4) * HID + o0 + og * 4;
#pragma unroll
    for (int k = 0; k < 4; k++) {
        float4 v;
        unpack2(v.x, v.y, acc[0][k]);
        unpack2(v.z, v.w, acc[1][k]);
        *(float4*)(dst + (size_t)k * HID) = v;
    }
}

// ---- split-K reduce + SiLU + LayerNorm (+ classifier) ----
__global__ __launch_bounds__(128) void reduce_kernel(const float* __restrict__ gamma,
                                                     const float* __restrict__ beta,
                                                     const float* __restrict__ cw,
                                                     const float* __restrict__ cb,
                                                     float* __restrict__ out,
                                                     int outsel) {
    const int b = blockIdx.x;
    const int tid = threadIdx.x;
    const int wid = tid >> 5, lane = tid & 31;
    __shared__ float r1[4], r2[4];

    // independent prologue loads before grid-dep sync
    float4 gm = ((const float4*)gamma)[tid];
    float4 bt = ((const float4*)beta)[tid];
    float4 cwa = make_float4(0.f, 0.f, 0.f, 0.f), cwb = cwa;
    if (outsel == 0) {
        cwa = ((const float4*)cw)[tid];
        cwb = ((const float4*)(cw + HID))[tid];
    }
    cudaGridDependencySynchronize();   // wait for wav partials

    const float4* src = (const float4*)(g_part + (size_t)b * HID + tid * 4);
    float4 z = make_float4(0.f, 0.f, 0.f, 0.f);
#pragma unroll
    for (int k = 0; k < KS; k++) {
        float4 v = src[(size_t)k * (BATCH * HID / 4)];
        z.x += v.x; z.y += v.y; z.z += v.z; z.w += v.w;
    }
    float a[4];
    float lsum = 0.f, lsq = 0.f;
#pragma unroll
    for (int j = 0; j < 4; j++) {
        float zz = ((float*)&z)[j];
        float sig = 1.0f / (1.0f + __expf(-zz));
        float av = zz * sig;
        a[j] = av;
        lsum += av;
        lsq = fmaf(av, av, lsq);
    }
#pragma unroll
    for (int off = 16; off; off >>= 1) {
        lsum += __shfl_xor_sync(0xffffffffu, lsum, off);
        lsq  += __shfl_xor_sync(0xffffffffu, lsq, off);
    }
    if (lane == 0) { r1[wid] = lsum; r2[wid] = lsq; }
    __syncthreads();
    float tsum = r1[0] + r1[1] + r1[2] + r1[3];
    float tsq  = r2[0] + r2[1] + r2[2] + r2[3];
    float mean = tsum * (1.0f / HID);
    float var  = tsq * (1.0f / HID) - mean * mean;
    float rstd = rsqrtf(var + 1e-5f);

    float d0 = 0.f, d1 = 0.f;
    float* ft = (outsel == 1) ? g_f1t : g_f2t;
#pragma unroll
    for (int j = 0; j < 4; j++) {
        int o = tid * 4 + j;
        float y = (a[j] - mean) * rstd * ((float*)&gm)[j] + ((float*)&bt)[j];
        if (outsel == 0) {
            d0 = fmaf(y, ((float*)&cwa)[j], d0);
            d1 = fmaf(y, ((float*)&cwb)[j], d1);
        } else {
            ft[(size_t)o * BATCH + b] = y;
        }
    }
    if (outsel == 0) {
#pragma unroll
        for (int off = 16; off; off >>= 1) {
            d0 += __shfl_xor_sync(0xffffffffu, d0, off);
            d1 += __shfl_xor_sync(0xffffffffu, d1, off);
        }
        __syncthreads();
        if (lane == 0) { r1[wid] = d0; r2[wid] = d1; }
        __syncthreads();
        if (tid == 0) {
            out[b * 2 + 0] = r1[0] + r1[1] + r1[2] + r1[3] + cb[0];
            out[b * 2 + 1] = r2[0] + r2[1] + r2[2] + r2[3] + cb[1];
        }
    }
}

// helper: launch with PDL (programmatic stream serialization)
template <typename... Args>
static void launch_pdl(void (*kern)(Args...), dim3 grid, dim3 block, Args... args) {
    cudaLaunchConfig_t cfg = {};
    cfg.gridDim = grid;
    cfg.blockDim = block;
    cfg.dynamicSmemBytes = 0;
    cfg.stream = 0;
    cudaLaunchAttribute attr[1];
    attr[0].id = cudaLaunchAttributeProgrammaticStreamSerialization;
    attr[0].val.programmaticStreamSerializationAllowed = 1;
    cfg.attrs = attr;
    cfg.numAttrs = 1;
    cudaLaunchKernelEx(&cfg, kern, args...);
}

extern "C" void kernel_launch(void* const* d_in, const int* in_sizes, int n_in,
                              void* d_out, int out_size) {
    const float* x  = (const float*)d_in[0];
    const float* t0 = (const float*)d_in[1];
    const float* s0 = (const float*)d_in[2];
    const float* w0 = (const float*)d_in[3];
    const float* g0 = (const float*)d_in[4];
    const float* b0 = (const float*)d_in[5];
    const float* t1 = (const float*)d_in[6];
    const float* s1 = (const float*)d_in[7];
    const float* w1 = (const float*)d_in[8];
    const float* g1 = (const float*)d_in[9];
    const float* b1 = (const float*)d_in[10];
    const float* t2 = (const float*)d_in[11];
    const float* s2 = (const float*)d_in[12];
    const float* w2 = (const float*)d_in[13];
    const float* g2 = (const float*)d_in[14];
    const float* b2 = (const float*)d_in[15];
    const float* cw = (const float*)d_in[16];
    const float* cb = (const float*)d_in[17];
    float* out = (float*)d_out;

    setup_kernel<<<2048, dim3(32, 8)>>>(t0, s0, w0, t1, s1, w1, t2, s2, w2, x);

    dim3 gw(HID / OBLK, BATCH / BBLK, KS);  // (8, 8, 32) = 2048 blocks
    dim3 bw(128, 1, 1);
    dim3 gr(BATCH, 1, 1);

    launch_pdl(wav_kernel, gw, bw, DIN, 0, 0, DIN / KS);
    launch_pdl(reduce_kernel, gr, bw, g0, b0, cw, cb, out, 1);

    launch_pdl(wav_kernel, gw, bw, HID, OFF1, 1, HID / KS);
    launch_pdl(reduce_kernel, gr, bw, g1, b1, cw, cb, out, 2);

    launch_pdl(wav_kernel, gw, bw, HID, OFF2, 2, HID / KS);
    launch_pdl(reduce_kernel, gr, bw, g2, b2, cw, cb, out, 0);
}